// round 6
// baseline (speedup 1.0000x reference)
#include <cuda_runtime.h>
#include <cuda_bf16.h>
#include <math.h>
#include <float.h>
#include <stdint.h>

#define BB 32768
#define DD 256
#define KK 4096
#define NPOOL 24   // 8 threads/row x top-3

// ---- scratch (static device globals: allocation-free) ----
__device__ float          g_wsq[KK];
__device__ unsigned int   g_counts[KK];
__device__ double         g_loss;
__device__ signed char    g_w8[KK * DD];     // s8(round(w * 4096 * 127))
__device__ float          g_cval[BB * NPOOL];
__device__ int            g_cidx[BB * NPOOL];

// ---------------- helpers ----------------
__device__ __forceinline__ uint32_t smem_u32(const void* p) {
    return (uint32_t)__cvta_generic_to_shared(p);
}
__device__ __forceinline__ void cp16(uint32_t dst, const void* src) {
    asm volatile("cp.async.cg.shared.global [%0], [%1], 16;" :: "r"(dst), "l"(src));
}
__device__ __forceinline__ void cp_commit() {
    asm volatile("cp.async.commit_group;" ::: "memory");
}
template <int N> __device__ __forceinline__ void cp_wait() {
    asm volatile("cp.async.wait_group %0;" :: "n"(N) : "memory");
}
__device__ __forceinline__ uint32_t swz(uint32_t off) {
    return off ^ ((off >> 3) & 0x70);
}
__device__ __forceinline__ void ldsm4(uint32_t* r, uint32_t addr) {
    asm volatile("ldmatrix.sync.aligned.m8n8.x4.shared.b16 {%0,%1,%2,%3}, [%4];"
                 : "=r"(r[0]), "=r"(r[1]), "=r"(r[2]), "=r"(r[3]) : "r"(addr));
}
__device__ __forceinline__ void imma16832(int* c, const uint32_t* a,
                                          const uint32_t* b) {
    asm volatile(
        "mma.sync.aligned.m16n8k32.row.col.s32.s8.s8.s32 "
        "{%0,%1,%2,%3}, {%4,%5,%6,%7}, {%8,%9}, {%0,%1,%2,%3};"
        : "+r"(c[0]), "+r"(c[1]), "+r"(c[2]), "+r"(c[3])
        : "r"(a[0]), "r"(a[1]), "r"(a[2]), "r"(a[3]), "r"(b[0]), "r"(b[1]));
}
// pack 4 floats (pre-scaled) -> 4 s8 bytes, byte0 = f0
__device__ __forceinline__ uint32_t pack4_s8(float f0, float f1, float f2,
                                             float f3) {
    int a = __float2int_rn(f0), b = __float2int_rn(f1);
    int c = __float2int_rn(f2), d = __float2int_rn(f3);
    return (uint32_t)(a & 0xff) | ((uint32_t)(b & 0xff) << 8) |
           ((uint32_t)(c & 0xff) << 16) | ((uint32_t)(d & 0xff) << 24);
}

// ---------------- pass-1 smem layout (bytes) ----------------
// z s8: 2 slices x [128 rows x 128B] = 32768 ; w ring: 2 x 16384 = 32768
#define ZH_OFF    0u
#define W_OFF     32768u
#define SMEM_BYTES 65536u

// ---------------------------------------------------------------------------
// Kernel A: codebook -> s8 (scaled by 4096*127), fp32 norms, zero accums.
// |w|*4096 < 1 so |w*4096*127| < 127: no clamping needed.
// ---------------------------------------------------------------------------
__global__ void conv_w(const float* __restrict__ cb) {
    int r = blockIdx.x * 8 + (threadIdx.x >> 5);
    int lane = threadIdx.x & 31;
    const float* wr = cb + (size_t)r * DD + lane * 8;
    float4 a = *(const float4*)wr;
    float4 b = *(const float4*)(wr + 4);
    float s = a.x * a.x + a.y * a.y + a.z * a.z + a.w * a.w +
              b.x * b.x + b.y * b.y + b.z * b.z + b.w * b.w;
    const float sc = 4096.f * 127.f;
    uint2 pk;
    pk.x = pack4_s8(a.x * sc, a.y * sc, a.z * sc, a.w * sc);
    pk.y = pack4_s8(b.x * sc, b.y * sc, b.z * sc, b.w * sc);
    *(uint2*)(g_w8 + (size_t)r * DD + lane * 8) = pk;
    #pragma unroll
    for (int o = 16; o > 0; o >>= 1) s += __shfl_xor_sync(0xffffffffu, s, o);
    if (lane == 0) { g_wsq[r] = s; g_counts[r] = 0u; }
    if (r == 0 && lane == 0) g_loss = 0.0;
}

// ---------------------------------------------------------------------------
// w-slice loader: slice j = (chunk j>>1, dslice j&1): 128 codes x 128 dims s8.
// ---------------------------------------------------------------------------
__device__ __forceinline__ void load_wslice(int j, int bufj, uint32_t sb, int tid) {
    const int ch = j >> 1, s = j & 1;
    const uint32_t base = sb + W_OFF + (uint32_t)bufj * 16384u;
    #pragma unroll
    for (int i = 0; i < 4; ++i) {
        int flat = i * 256 + tid;        // 1024 16B-chunks
        int n = flat >> 3, c = flat & 7;
        uint32_t off = swz((uint32_t)(n * 128 + c * 16));
        cp16(base + off, g_w8 + (size_t)(ch * 128 + n) * DD + s * 128 + c * 16);
    }
}

// ---------------------------------------------------------------------------
// Pass 1: s8 IMMA GEMM; per-thread top-3 (by int dot) candidate pool.
// z quantized per-row (ranking-invariant). 8 warps = 4(M) x 2(N), 2 CTAs/SM.
// ---------------------------------------------------------------------------
__global__ void __launch_bounds__(256, 2)
vq_pass1(const float* __restrict__ z) {
    extern __shared__ __align__(1024) char smem[];
    const uint32_t sb = smem_u32(smem);
    const int tid = threadIdx.x;
    const int lane = tid & 31;
    const int warp = tid >> 5;
    const int wm = warp >> 1;        // 0..3 (M)
    const int wn = warp & 1;         // 0..1 (N)
    const int g = lane >> 3;
    const int l7 = lane & 7;
    const int row0 = blockIdx.x * 128;

    // prefetch w slices 0,1
    load_wslice(0, 0, sb, tid); cp_commit();
    load_wslice(1, 1, sb, tid); cp_commit();

    // ---- stage z fp32 -> s8 with per-row scale (2 threads per row) ----
    {
        const int r = tid >> 1, half = tid & 1;
        const float4* zp = (const float4*)(z + (size_t)(row0 + r) * DD + half * 128);
        float m = 0.f;
        #pragma unroll
        for (int c = 0; c < 32; ++c) {
            float4 v = zp[c];
            m = fmaxf(m, fmaxf(fmaxf(fabsf(v.x), fabsf(v.y)),
                               fmaxf(fabsf(v.z), fabsf(v.w))));
        }
        m = fmaxf(m, __shfl_xor_sync(0xffffffffu, m, 1));   // row max
        const float scale = 127.f / m;
        #pragma unroll
        for (int c8 = 0; c8 < 8; ++c8) {       // 8 chunks of 16 dims
            float4 v0 = zp[c8 * 4 + 0];
            float4 v1 = zp[c8 * 4 + 1];
            float4 v2 = zp[c8 * 4 + 2];
            float4 v3 = zp[c8 * 4 + 3];
            uint4 pk;
            pk.x = pack4_s8(v0.x * scale, v0.y * scale, v0.z * scale, v0.w * scale);
            pk.y = pack4_s8(v1.x * scale, v1.y * scale, v1.z * scale, v1.w * scale);
            pk.z = pack4_s8(v2.x * scale, v2.y * scale, v2.z * scale, v2.w * scale);
            pk.w = pack4_s8(v3.x * scale, v3.y * scale, v3.z * scale, v3.w * scale);
            uint32_t off = swz((uint32_t)(r * 128 + c8 * 16))
                           + (uint32_t)(half * 16384);
            *(uint4*)(smem + ZH_OFF + off) = pk;
        }
    }

    int b0v[4], b1v[4], b2v[4];
    int b0i[4], b1i[4], b2i[4];
    #pragma unroll
    for (int i = 0; i < 4; ++i) {
        b0v[i] = INT_MIN; b1v[i] = INT_MIN; b2v[i] = INT_MIN;
        b0i[i] = 0; b1i[i] = 0; b2i[i] = 0;
    }

    int acc[2][8][4];

    for (int idx = 0; idx < 64; ++idx) {
        const int ch = idx >> 1, s = idx & 1, buf = idx & 1;

        cp_wait<1>();
        __syncthreads();

        if (s == 0) {
            #pragma unroll
            for (int mf = 0; mf < 2; ++mf)
                #pragma unroll
                for (int nf = 0; nf < 8; ++nf)
                    #pragma unroll
                    for (int q = 0; q < 4; ++q) acc[mf][nf][q] = 0;
        }

        const uint32_t wbase = sb + W_OFF + (uint32_t)buf * 16384u;
        #pragma unroll
        for (int ks = 0; ks < 4; ++ks) {
            uint32_t ah[2][4];
            #pragma unroll
            for (int mf = 0; mf < 2; ++mf) {
                uint32_t off = (uint32_t)((wm * 32 + mf * 16 + (g & 1) * 8 + l7) * 128
                                          + ks * 32 + ((g >> 1) << 4));
                ldsm4(ah[mf], sb + ZH_OFF + swz(off) + (uint32_t)(s * 16384));
            }
            uint32_t bh[4][4];
            #pragma unroll
            for (int p = 0; p < 4; ++p) {
                uint32_t off = (uint32_t)((wn * 64 + p * 16 + ((g >> 1) << 3) + l7) * 128
                                          + ks * 32 + ((g & 1) << 4));
                ldsm4(bh[p], wbase + swz(off));
            }
            #pragma unroll
            for (int mf = 0; mf < 2; ++mf)
                #pragma unroll
                for (int p = 0; p < 4; ++p) {
                    imma16832(acc[mf][2 * p],     ah[mf], &bh[p][0]);
                    imma16832(acc[mf][2 * p + 1], ah[mf], &bh[p][2]);
                }
        }

        __syncthreads();
        if (idx + 2 < 64) load_wslice(idx + 2, buf, sb, tid);
        cp_commit();

        if (s == 1) {
            // per-(thread,row-slot) top-3 by int dot (bigger = closer)
            #pragma unroll
            for (int nf = 0; nf < 8; ++nf) {
                int col0 = ch * 128 + wn * 64 + nf * 8 + (lane & 3) * 2;
                #pragma unroll
                for (int mf = 0; mf < 2; ++mf) {
                    #pragma unroll
                    for (int q = 0; q < 4; ++q) {
                        int sl = mf * 2 + (q >> 1);
                        int v = acc[mf][nf][q];
                        int c = col0 + (q & 1);
                        if (v > b2v[sl]) {
                            if (v > b1v[sl]) {
                                b2v[sl] = b1v[sl]; b2i[sl] = b1i[sl];
                                if (v > b0v[sl]) {
                                    b1v[sl] = b0v[sl]; b1i[sl] = b0i[sl];
                                    b0v[sl] = v;       b0i[sl] = c;
                                } else { b1v[sl] = v; b1i[sl] = c; }
                            } else { b2v[sl] = v; b2i[sl] = c; }
                        }
                    }
                }
            }
        }
    }

    // write 3 candidates per (thread, row-slot) -> 24 per row
    #pragma unroll
    for (int sl = 0; sl < 4; ++sl) {
        int r = row0 + wm * 32 + (sl >> 1) * 16 + (sl & 1) * 8 + (lane >> 2);
        int base = r * NPOOL + (wn * 4 + (lane & 3)) * 3;
        g_cval[base]     = (float)b0v[sl]; g_cidx[base]     = b0i[sl];
        g_cval[base + 1] = (float)b1v[sl]; g_cidx[base + 1] = b1i[sl];
        g_cval[base + 2] = (float)b2v[sl]; g_cidx[base + 2] = b2i[sl];
    }
}

// ---------------------------------------------------------------------------
// Pass 2 (fused output): per row, exact fp32 rescore of the top-8 pool
// candidates with reference rounding fl(fl(zsq+wsq) - 2*dot) and first-index
// tie-break; write z_q, index, histogram, loss partials. One warp per row.
// NOTE: dot/zsq summation orders identical to rounds 3-5 (proven vs reference).
// ---------------------------------------------------------------------------
__global__ void __launch_bounds__(256)
vq_rescore(const float* __restrict__ z, const float* __restrict__ cb,
           float* __restrict__ out, int out_size) {
    const int lane = threadIdx.x & 31;
    const int row = blockIdx.x * 8 + (threadIdx.x >> 5);

    // z row: 8 dims per lane
    float zr[8];
    {
        float4 a = *(const float4*)(z + (size_t)row * DD + lane * 8);
        float4 b = *(const float4*)(z + (size_t)row * DD + lane * 8 + 4);
        zr[0] = a.x; zr[1] = a.y; zr[2] = a.z; zr[3] = a.w;
        zr[4] = b.x; zr[5] = b.y; zr[6] = b.z; zr[7] = b.w;
    }
    float zsq = 0.f;
    #pragma unroll
    for (int k = 0; k < 8; ++k) zsq += zr[k] * zr[k];
    #pragma unroll
    for (int o = 16; o > 0; o >>= 1) zsq += __shfl_xor_sync(0xffffffffu, zsq, o);

    // candidate pool
    float cv = -FLT_MAX; int ci = 0x7fffffff;
    if (lane < NPOOL) { cv = g_cval[row * NPOOL + lane]; ci = g_cidx[row * NPOOL + lane]; }

    float bdist = FLT_MAX;
    int   widx = 0x7fffffff;
    #pragma unroll
    for (int t = 0; t < 8; ++t) {
        // argmax of remaining approx dots (tie -> smaller index)
        float m = cv; int mi = ci;
        #pragma unroll
        for (int o = 16; o > 0; o >>= 1) {
            float mv = __shfl_xor_sync(0xffffffffu, m, o);
            int   mj = __shfl_xor_sync(0xffffffffu, mi, o);
            if (mv > m || (mv == m && mj < mi)) { m = mv; mi = mj; }
        }
        if (ci == mi) cv = -FLT_MAX;   // consume

        // exact fp32 rescore of candidate mi
        const float* wp = cb + (size_t)mi * DD + lane * 8;
        float4 a = *(const float4*)wp;
        float4 b = *(const float4*)(wp + 4);
        float d = 0.f;
        d = fmaf(zr[0], a.x, d); d = fmaf(zr[1], a.y, d);
        d = fmaf(zr[2], a.z, d); d = fmaf(zr[3], a.w, d);
        d = fmaf(zr[4], b.x, d); d = fmaf(zr[5], b.y, d);
        d = fmaf(zr[6], b.z, d); d = fmaf(zr[7], b.w, d);
        #pragma unroll
        for (int o = 16; o > 0; o >>= 1) d += __shfl_xor_sync(0xffffffffu, d, o);
        float dist = (zsq + __ldg(&g_wsq[mi])) - 2.f * d;
        if (dist < bdist || (dist == bdist && mi < widx)) { bdist = dist; widx = mi; }
    }

    // outputs: gather winner row
    const float* wp = cb + (size_t)widx * DD + lane * 8;
    float4 a = *(const float4*)wp;
    float4 b = *(const float4*)(wp + 4);
    float lsum = 0.f;
    {
        float* op = out + (size_t)row * DD + lane * 8;
        if ((row + 1) * DD <= out_size) {
            *(float4*)op = a;
            *(float4*)(op + 4) = b;
        }
        float w8[8] = {a.x, a.y, a.z, a.w, b.x, b.y, b.z, b.w};
        #pragma unroll
        for (int k = 0; k < 8; ++k) {
            float dd = w8[k] - zr[k];
            lsum += dd * dd;
        }
    }
    #pragma unroll
    for (int o = 16; o > 0; o >>= 1) lsum += __shfl_xor_sync(0xffffffffu, lsum, o);

    if (lane == 0) {
        atomicAdd(&g_counts[widx], 1u);
        atomicAdd(&g_loss, (double)lsum);
        int pos = BB * DD + row;
        if (pos < out_size) out[pos] = (float)widx;
    }
}

// ---------------------------------------------------------------------------
// Finalize scalars.
// ---------------------------------------------------------------------------
__global__ void vq_final(float* __restrict__ out, int out_size) {
    __shared__ double red[32];
    int t = threadIdx.x;
    double s = 0.0;
    for (int k = t; k < KK; k += 1024) {
        float p = (float)g_counts[k] / (float)BB;
        s += (double)(p * logf(p + 1e-10f));
    }
    #pragma unroll
    for (int o = 16; o > 0; o >>= 1) s += __shfl_xor_sync(0xffffffffu, s, o);
    if ((t & 31) == 0) red[t >> 5] = s;
    __syncthreads();
    if (t < 32) {
        double v = red[t];
        #pragma unroll
        for (int o = 16; o > 0; o >>= 1) v += __shfl_xor_sync(0xffffffffu, v, o);
        if (t == 0) {
            int p0 = BB * DD + BB;
            if (p0 < out_size)
                out[p0] = (float)(g_loss / ((double)BB * (double)DD) * 1.25);
            if (p0 + 1 < out_size)
                out[p0 + 1] = expf((float)(-v));
        }
    }
}

// ---------------------------------------------------------------------------
extern "C" void kernel_launch(void* const* d_in, const int* in_sizes, int n_in,
                              void* d_out, int out_size) {
    const float* z  = (const float*)d_in[0];   // z_e [32768, 256] f32
    const float* cb = (const float*)d_in[1];   // codebook [4096, 256] f32
    float* out = (float*)d_out;

    cudaFuncSetAttribute(vq_pass1,
                         cudaFuncAttributeMaxDynamicSharedMemorySize, SMEM_BYTES);

    conv_w<<<KK / 8, 256>>>(cb);
    vq_pass1<<<BB / 128, 256, SMEM_BYTES>>>(z);
    vq_rescore<<<BB / 8, 256>>>(z, cb, out, out_size);
    vq_final<<<1, 1024>>>(out, out_size);
}

// round 7
// speedup vs baseline: 2.3206x; 2.3206x over previous
#include <cuda_runtime.h>
#include <cuda_fp16.h>
#include <math.h>
#include <float.h>
#include <stdint.h>

#define BB 32768
#define DD 256
#define KK 4096
#define NPOOL 24   // 8 threads/row x top-3

// ---- scratch (static device globals: allocation-free) ----
__device__ float          g_wsq[KK];
__device__ unsigned int   g_counts[KK];
__device__ double         g_loss;
__device__ __half         g_w16[KK * DD];    // f16(w * 4096)
__device__ float          g_cval[BB * NPOOL];
__device__ int            g_cidx[BB * NPOOL];

// ---------------- helpers ----------------
__device__ __forceinline__ uint32_t smem_u32(const void* p) {
    return (uint32_t)__cvta_generic_to_shared(p);
}
__device__ __forceinline__ void cp16(uint32_t dst, const void* src) {
    asm volatile("cp.async.cg.shared.global [%0], [%1], 16;" :: "r"(dst), "l"(src));
}
__device__ __forceinline__ void cp_commit() {
    asm volatile("cp.async.commit_group;" ::: "memory");
}
template <int N> __device__ __forceinline__ void cp_wait() {
    asm volatile("cp.async.wait_group %0;" :: "n"(N) : "memory");
}
__device__ __forceinline__ uint32_t swz(uint32_t off) {
    return off ^ ((off >> 3) & 0x70);
}
__device__ __forceinline__ void ldsm4(uint32_t* r, uint32_t addr) {
    asm volatile("ldmatrix.sync.aligned.m8n8.x4.shared.b16 {%0,%1,%2,%3}, [%4];"
                 : "=r"(r[0]), "=r"(r[1]), "=r"(r[2]), "=r"(r[3]) : "r"(addr));
}
// f16 inputs, f16 accumulators (2 regs)
__device__ __forceinline__ void mma16816h(uint32_t* c, const uint32_t* a,
                                          const uint32_t* b) {
    asm volatile(
        "mma.sync.aligned.m16n8k16.row.col.f16.f16.f16.f16 "
        "{%0,%1}, {%2,%3,%4,%5}, {%6,%7}, {%0,%1};"
        : "+r"(c[0]), "+r"(c[1])
        : "r"(a[0]), "r"(a[1]), "r"(a[2]), "r"(a[3]), "r"(b[0]), "r"(b[1]));
}

// ---------------- pass-1 smem layout (bytes) ----------------
// z f16: 4 slices x [128 rows x 64 f16] = 65536 ; w ring: 2 x 16384 = 32768
#define ZH_OFF    0u
#define W_OFF     65536u
#define SMEM_BYTES 98304u

// ---------------------------------------------------------------------------
// Kernel A: codebook -> f16 (scaled by 4096), fp32 norms, zero accumulators.
// ---------------------------------------------------------------------------
__global__ void conv_w(const float* __restrict__ cb) {
    int r = blockIdx.x * 8 + (threadIdx.x >> 5);
    int lane = threadIdx.x & 31;
    const float* wr = cb + (size_t)r * DD + lane * 8;
    float4 a = *(const float4*)wr;
    float4 b = *(const float4*)(wr + 4);
    float s = a.x * a.x + a.y * a.y + a.z * a.z + a.w * a.w +
              b.x * b.x + b.y * b.y + b.z * b.z + b.w * b.w;
    const float sc = 4096.f;
    __half2 h0 = __float22half2_rn(make_float2(a.x * sc, a.y * sc));
    __half2 h1 = __float22half2_rn(make_float2(a.z * sc, a.w * sc));
    __half2 h2 = __float22half2_rn(make_float2(b.x * sc, b.y * sc));
    __half2 h3 = __float22half2_rn(make_float2(b.z * sc, b.w * sc));
    uint4 pk;
    pk.x = *(uint32_t*)&h0; pk.y = *(uint32_t*)&h1;
    pk.z = *(uint32_t*)&h2; pk.w = *(uint32_t*)&h3;
    *(uint4*)(g_w16 + (size_t)r * DD + lane * 8) = pk;
    #pragma unroll
    for (int o = 16; o > 0; o >>= 1) s += __shfl_xor_sync(0xffffffffu, s, o);
    if (lane == 0) { g_wsq[r] = s; g_counts[r] = 0u; }
    if (r == 0 && lane == 0) g_loss = 0.0;
}

// ---------------------------------------------------------------------------
// w-slice loader: slice j = (chunk j>>2, dslice j&3): 128 codes x 64 dims f16.
// ---------------------------------------------------------------------------
__device__ __forceinline__ void load_wslice(int j, int bufj, uint32_t sb, int tid) {
    const int ch = j >> 2, s = j & 3;
    const uint32_t base = sb + W_OFF + (uint32_t)bufj * 16384u;
    #pragma unroll
    for (int i = 0; i < 4; ++i) {
        int flat = i * 256 + tid;        // 1024 16B-chunks
        int n = flat >> 3, c = flat & 7;
        uint32_t off = swz((uint32_t)(n * 128 + c * 16));
        cp16(base + off, g_w16 + (size_t)(ch * 128 + n) * DD + s * 64 + c * 8);
    }
}

// ---------------------------------------------------------------------------
// Pass 1: f16 mma (f16 accum) GEMM; per-thread top-3 candidate pool.
// 8 warps = 4(M) x 2(N), warp tile 32x64, 2 CTAs/SM.
// ---------------------------------------------------------------------------
__global__ void __launch_bounds__(256, 2)
vq_pass1(const float* __restrict__ z) {
    extern __shared__ __align__(1024) char smem[];
    const uint32_t sb = smem_u32(smem);
    const int tid = threadIdx.x;
    const int lane = tid & 31;
    const int warp = tid >> 5;
    const int wm = warp >> 1;        // 0..3 (M)
    const int wn = warp & 1;         // 0..1 (N)
    const int g = lane >> 3;
    const int l7 = lane & 7;
    const int row0 = blockIdx.x * 128;

    // prefetch w slices 0,1
    load_wslice(0, 0, sb, tid); cp_commit();
    load_wslice(1, 1, sb, tid); cp_commit();

    // ---- stage z fp32 -> f16 into smem (fused conversion) ----
    #pragma unroll
    for (int i = 0; i < 32; ++i) {
        int flat = i * 256 + tid;            // 8192 float4
        int r = flat >> 6, d4 = flat & 63;
        float4 v = *(const float4*)(z + (size_t)(row0 + r) * DD + d4 * 4);
        __half2 p0 = __float22half2_rn(make_float2(v.x, v.y));
        __half2 p1 = __float22half2_rn(make_float2(v.z, v.w));
        uint2 pk;
        pk.x = *(uint32_t*)&p0; pk.y = *(uint32_t*)&p1;
        uint32_t off = swz((uint32_t)((d4 >> 4) * 16384 + r * 128 + (d4 & 15) * 8));
        *(uint2*)(smem + ZH_OFF + off) = pk;
    }

    float b0v[4], b1v[4], b2v[4];
    int   b0i[4], b1i[4], b2i[4];
    #pragma unroll
    for (int i = 0; i < 4; ++i) {
        b0v[i] = -FLT_MAX; b1v[i] = -FLT_MAX; b2v[i] = -FLT_MAX;
        b0i[i] = 0; b1i[i] = 0; b2i[i] = 0;
    }

    uint32_t acc[2][8][2];   // f16x2 accumulators

    for (int idx = 0; idx < 128; ++idx) {
        const int ch = idx >> 2, s = idx & 3, buf = idx & 1;

        cp_wait<1>();
        __syncthreads();

        if (s == 0) {
            #pragma unroll
            for (int mf = 0; mf < 2; ++mf)
                #pragma unroll
                for (int nf = 0; nf < 8; ++nf) {
                    acc[mf][nf][0] = 0u; acc[mf][nf][1] = 0u;
                }
        }

        const uint32_t wbase = sb + W_OFF + (uint32_t)buf * 16384u;
        #pragma unroll
        for (int ks = 0; ks < 4; ++ks) {
            uint32_t ah[2][4];
            #pragma unroll
            for (int mf = 0; mf < 2; ++mf) {
                uint32_t off = (uint32_t)((wm * 32 + mf * 16 + (g & 1) * 8 + l7) * 128
                                          + ks * 32 + ((g >> 1) << 4));
                ldsm4(ah[mf], sb + ZH_OFF + swz(off) + (uint32_t)(s * 16384));
            }
            uint32_t bh[4][4];
            #pragma unroll
            for (int p = 0; p < 4; ++p) {
                uint32_t off = (uint32_t)((wn * 64 + p * 16 + ((g >> 1) << 3) + l7) * 128
                                          + ks * 32 + ((g & 1) << 4));
                ldsm4(bh[p], wbase + swz(off));
            }
            #pragma unroll
            for (int mf = 0; mf < 2; ++mf)
                #pragma unroll
                for (int p = 0; p < 4; ++p) {
                    mma16816h(acc[mf][2 * p],     ah[mf], &bh[p][0]);
                    mma16816h(acc[mf][2 * p + 1], ah[mf], &bh[p][2]);
                }
        }

        __syncthreads();
        if (idx + 2 < 128) load_wslice(idx + 2, buf, sb, tid);
        cp_commit();

        if (s == 3) {
            // per-(thread,row-slot) top-3 by scaled dot (bigger = closer)
            #pragma unroll
            for (int nf = 0; nf < 8; ++nf) {
                int col0 = ch * 128 + wn * 64 + nf * 8 + (lane & 3) * 2;
                #pragma unroll
                for (int mf = 0; mf < 2; ++mf) {
                    float2 p01 = __half22float2(*(__half2*)&acc[mf][nf][0]);
                    float2 p23 = __half22float2(*(__half2*)&acc[mf][nf][1]);
                    float vq[4] = {p01.x, p01.y, p23.x, p23.y};
                    #pragma unroll
                    for (int q = 0; q < 4; ++q) {
                        int sl = mf * 2 + (q >> 1);
                        float v = vq[q];
                        int c = col0 + (q & 1);
                        if (v > b2v[sl]) {
                            if (v > b1v[sl]) {
                                b2v[sl] = b1v[sl]; b2i[sl] = b1i[sl];
                                if (v > b0v[sl]) {
                                    b1v[sl] = b0v[sl]; b1i[sl] = b0i[sl];
                                    b0v[sl] = v;       b0i[sl] = c;
                                } else { b1v[sl] = v; b1i[sl] = c; }
                            } else { b2v[sl] = v; b2i[sl] = c; }
                        }
                    }
                }
            }
        }
    }

    // write 3 candidates per (thread, row-slot) -> 24 per row
    #pragma unroll
    for (int sl = 0; sl < 4; ++sl) {
        int r = row0 + wm * 32 + (sl >> 1) * 16 + (sl & 1) * 8 + (lane >> 2);
        int base = r * NPOOL + (wn * 4 + (lane & 3)) * 3;
        g_cval[base]     = b0v[sl]; g_cidx[base]     = b0i[sl];
        g_cval[base + 1] = b1v[sl]; g_cidx[base + 1] = b1i[sl];
        g_cval[base + 2] = b2v[sl]; g_cidx[base + 2] = b2i[sl];
    }
}

// ---------------------------------------------------------------------------
// Pass 2 (fused output): per row, exact fp32 rescore of the top-8 pool
// candidates with reference rounding fl(fl(zsq+wsq) - 2*dot) and first-index
// tie-break; write z_q, index, histogram, loss partials. One warp per row.
// NOTE: dot/zsq summation orders identical to rounds 3-6 (proven vs reference).
// ---------------------------------------------------------------------------
__global__ void __launch_bounds__(256)
vq_rescore(const float* __restrict__ z, const float* __restrict__ cb,
           float* __restrict__ out, int out_size) {
    const int lane = threadIdx.x & 31;
    const int row = blockIdx.x * 8 + (threadIdx.x >> 5);

    // z row: 8 dims per lane
    float zr[8];
    {
        float4 a = *(const float4*)(z + (size_t)row * DD + lane * 8);
        float4 b = *(const float4*)(z + (size_t)row * DD + lane * 8 + 4);
        zr[0] = a.x; zr[1] = a.y; zr[2] = a.z; zr[3] = a.w;
        zr[4] = b.x; zr[5] = b.y; zr[6] = b.z; zr[7] = b.w;
    }
    float zsq = 0.f;
    #pragma unroll
    for (int k = 0; k < 8; ++k) zsq += zr[k] * zr[k];
    #pragma unroll
    for (int o = 16; o > 0; o >>= 1) zsq += __shfl_xor_sync(0xffffffffu, zsq, o);

    // candidate pool
    float cv = -FLT_MAX; int ci = 0x7fffffff;
    if (lane < NPOOL) { cv = g_cval[row * NPOOL + lane]; ci = g_cidx[row * NPOOL + lane]; }

    float bdist = FLT_MAX;
    int   widx = 0x7fffffff;
    #pragma unroll
    for (int t = 0; t < 8; ++t) {
        // argmax of remaining approx dots (tie -> smaller index)
        float m = cv; int mi = ci;
        #pragma unroll
        for (int o = 16; o > 0; o >>= 1) {
            float mv = __shfl_xor_sync(0xffffffffu, m, o);
            int   mj = __shfl_xor_sync(0xffffffffu, mi, o);
            if (mv > m || (mv == m && mj < mi)) { m = mv; mi = mj; }
        }
        if (ci == mi) cv = -FLT_MAX;   // consume

        // exact fp32 rescore of candidate mi
        const float* wp = cb + (size_t)mi * DD + lane * 8;
        float4 a = *(const float4*)wp;
        float4 b = *(const float4*)(wp + 4);
        float d = 0.f;
        d = fmaf(zr[0], a.x, d); d = fmaf(zr[1], a.y, d);
        d = fmaf(zr[2], a.z, d); d = fmaf(zr[3], a.w, d);
        d = fmaf(zr[4], b.x, d); d = fmaf(zr[5], b.y, d);
        d = fmaf(zr[6], b.z, d); d = fmaf(zr[7], b.w, d);
        #pragma unroll
        for (int o = 16; o > 0; o >>= 1) d += __shfl_xor_sync(0xffffffffu, d, o);
        float dist = (zsq + __ldg(&g_wsq[mi])) - 2.f * d;
        if (dist < bdist || (dist == bdist && mi < widx)) { bdist = dist; widx = mi; }
    }

    // outputs: gather winner row
    const float* wp = cb + (size_t)widx * DD + lane * 8;
    float4 a = *(const float4*)wp;
    float4 b = *(const float4*)(wp + 4);
    float lsum = 0.f;
    {
        float* op = out + (size_t)row * DD + lane * 8;
        if ((row + 1) * DD <= out_size) {
            *(float4*)op = a;
            *(float4*)(op + 4) = b;
        }
        float w8[8] = {a.x, a.y, a.z, a.w, b.x, b.y, b.z, b.w};
        #pragma unroll
        for (int k = 0; k < 8; ++k) {
            float dd = w8[k] - zr[k];
            lsum += dd * dd;
        }
    }
    #pragma unroll
    for (int o = 16; o > 0; o >>= 1) lsum += __shfl_xor_sync(0xffffffffu, lsum, o);

    if (lane == 0) {
        atomicAdd(&g_counts[widx], 1u);
        atomicAdd(&g_loss, (double)lsum);
        int pos = BB * DD + row;
        if (pos < out_size) out[pos] = (float)widx;
    }
}

// ---------------------------------------------------------------------------
// Finalize scalars.
// ---------------------------------------------------------------------------
__global__ void vq_final(float* __restrict__ out, int out_size) {
    __shared__ double red[32];
    int t = threadIdx.x;
    double s = 0.0;
    for (int k = t; k < KK; k += 1024) {
        float p = (float)g_counts[k] / (float)BB;
        s += (double)(p * logf(p + 1e-10f));
    }
    #pragma unroll
    for (int o = 16; o > 0; o >>= 1) s += __shfl_xor_sync(0xffffffffu, s, o);
    if ((t & 31) == 0) red[t >> 5] = s;
    __syncthreads();
    if (t < 32) {
        double v = red[t];
        #pragma unroll
        for (int o = 16; o > 0; o >>= 1) v += __shfl_xor_sync(0xffffffffu, v, o);
        if (t == 0) {
            int p0 = BB * DD + BB;
            if (p0 < out_size)
                out[p0] = (float)(g_loss / ((double)BB * (double)DD) * 1.25);
            if (p0 + 1 < out_size)
                out[p0 + 1] = expf((float)(-v));
        }
    }
}

// ---------------------------------------------------------------------------
extern "C" void kernel_launch(void* const* d_in, const int* in_sizes, int n_in,
                              void* d_out, int out_size) {
    const float* z  = (const float*)d_in[0];   // z_e [32768, 256] f32
    const float* cb = (const float*)d_in[1];   // codebook [4096, 256] f32
    float* out = (float*)d_out;

    cudaFuncSetAttribute(vq_pass1,
                         cudaFuncAttributeMaxDynamicSharedMemorySize, SMEM_BYTES);

    conv_w<<<KK / 8, 256>>>(cb);
    vq_pass1<<<BB / 128, 256, SMEM_BYTES>>>(z);
    vq_rescore<<<BB / 8, 256>>>(z, cb, out, out_size);
    vq_final<<<1, 1024>>>(out, out_size);
}